// round 13
// baseline (speedup 1.0000x reference)
#include <cuda_runtime.h>
#include <cuda_bf16.h>
#include <math.h>

typedef unsigned int uint32;

// ============================================================================
// HeadGroupedFusionGate, mma.sync bf16 3-term split (x*w ~ xh*wh + xl*wh + xh*wl).
// R13: warp-specialized k_tail. 384 thr = 8 consumer warps (ldsm+mma only) +
//      4 producer warps (LDG+stats+cvt+STS, double-buffered A; bulk-DMA B),
//      coupled by mbarrier full/empty pairs. No A gmem round trip (R12's
//      regression). k_pre = R11 (hidden GEMM + weight prep).
// ============================================================================

__device__ uint4 g_WhV[21 * 1088];    // B: [chunk][k=64][n=136 pad] bf16
__device__ uint4 g_WlV[21 * 1088];
__device__ float g_hidc[2][4096 * 128];

// ---- PTX helpers ----
__device__ __forceinline__ uint32 smem_u32(const void* p) {
    uint32 a;
    asm("{ .reg .u64 t; cvta.to.shared.u64 t, %1; cvt.u32.u64 %0, t; }" : "=r"(a) : "l"(p));
    return a;
}
__device__ __forceinline__ void ldsm4(uint32* r, uint32 a) {
    asm volatile("ldmatrix.sync.aligned.m8n8.x4.shared.b16 {%0,%1,%2,%3}, [%4];"
        : "=r"(r[0]), "=r"(r[1]), "=r"(r[2]), "=r"(r[3]) : "r"(a));
}
__device__ __forceinline__ void ldsm4t(uint32* r, uint32 a) {
    asm volatile("ldmatrix.sync.aligned.m8n8.x4.trans.shared.b16 {%0,%1,%2,%3}, [%4];"
        : "=r"(r[0]), "=r"(r[1]), "=r"(r[2]), "=r"(r[3]) : "r"(a));
}
__device__ __forceinline__ void mma16816(float* d, const uint32* a, uint32 b0, uint32 b1) {
    asm volatile("mma.sync.aligned.m16n8k16.row.col.f32.bf16.bf16.f32 "
        "{%0,%1,%2,%3}, {%4,%5,%6,%7}, {%8,%9}, {%0,%1,%2,%3};"
        : "+f"(d[0]), "+f"(d[1]), "+f"(d[2]), "+f"(d[3])
        : "r"(a[0]), "r"(a[1]), "r"(a[2]), "r"(a[3]), "r"(b0), "r"(b1));
}
__device__ __forceinline__ void cvtpair(float v0, float v1, uint32& h, uint32& l) {
    __nv_bfloat162 hp = __floats2bfloat162_rn(v0, v1);
    h = *(uint32*)&hp;
    float r0 = v0 - __bfloat162float(hp.x);
    float r1 = v1 - __bfloat162float(hp.y);
    __nv_bfloat162 lp = __floats2bfloat162_rn(r0, r1);
    l = *(uint32*)&lp;
}
#define MBAR_INIT(mb, n) \
    asm volatile("mbarrier.init.shared.b64 [%0], %1;" :: "r"(mb), "r"(n) : "memory")
#define MBAR_EXPECT(mb, tx) \
    asm volatile("mbarrier.arrive.expect_tx.shared.b64 _, [%0], %1;" :: "r"(mb), "r"(tx) : "memory")
#define MBAR_ARRIVE(mb) \
    asm volatile("mbarrier.arrive.shared.b64 _, [%0];" :: "r"(mb) : "memory")
__device__ __forceinline__ void bulk_cp(uint32 dst, const void* src, uint32 bytes, uint32 mb) {
    asm volatile("cp.async.bulk.shared::cta.global.mbarrier::complete_tx::bytes "
                 "[%0], [%1], %2, [%3];" :: "r"(dst), "l"(src), "r"(bytes), "r"(mb) : "memory");
}
__device__ __forceinline__ void mbar_wait(uint32 mb, uint32 parity) {
    asm volatile(
        "{\n\t.reg .pred P;\n\t"
        "W%=:\n\tmbarrier.try_wait.parity.acquire.cta.shared::cta.b64 P, [%0], %1, 0x989680;\n\t"
        "@P bra.uni D%=;\n\tbra.uni W%=;\n\tD%=:\n\t}"
        :: "r"(mb), "r"(parity) : "memory");
}

// warp tile 32 rows x 32 cols; NK k16 steps; low-register (one 16-col B half live).
template <int NK, int SA>
__device__ __forceinline__ void mma_chunk(float (&acc)[2][4][4],
                                          uint32 Ah, uint32 Al,
                                          uint32 Bh, uint32 Bl, int lane) {
    uint32 aoff = (uint32)((lane & 15) * SA + (lane >> 4) * 16);
    uint32 boff = (uint32)(((lane & 7) + ((lane >> 3) & 1) * 8) * 272 + ((lane >> 4) & 1) * 16);
#pragma unroll
    for (int k = 0; k < NK; ++k) {
        uint32 ah[2][4], al[2][4];
        ldsm4(ah[0], Ah + aoff + k * 32);
        ldsm4(ah[1], Ah + 16 * SA + aoff + k * 32);
        ldsm4(al[0], Al + aoff + k * 32);
        ldsm4(al[1], Al + 16 * SA + aoff + k * 32);
        uint32 bb = boff + k * 4352;
#pragma unroll
        for (int half = 0; half < 2; ++half) {
            uint32 bh[4], bl[4];
            ldsm4t(bh, Bh + bb + half * 32);
            ldsm4t(bl, Bl + bb + half * 32);
#pragma unroll
            for (int m = 0; m < 2; ++m) {
                mma16816(acc[m][2 * half + 0], ah[m], bh[0], bh[1]);
                mma16816(acc[m][2 * half + 1], ah[m], bh[2], bh[3]);
                mma16816(acc[m][2 * half + 0], al[m], bh[0], bh[1]);
                mma16816(acc[m][2 * half + 1], al[m], bh[2], bh[3]);
                mma16816(acc[m][2 * half + 0], ah[m], bl[0], bl[1]);
                mma16816(acc[m][2 * half + 1], ah[m], bl[2], bl[3]);
            }
        }
    }
}

// ============================================================================
// k_pre (R11): blocks 0..127 hidden GEMM, 128..172 tail-weight prep.
// smem (hid): AHI 0 (9216) | ALO 9216 | BH 18432 (17408) | BL 35840. = 53248.
// ============================================================================
#define P_ALO  9216
#define P_BH   18432
#define P_BL   35840
#define P_SMEM 53248

__global__ void __launch_bounds__(256) k_pre(const float* __restrict__ hidden,
                                             const float* __restrict__ W1) {
    int tid = threadIdx.x;
    if (blockIdx.x >= 128) {
        int b2 = blockIdx.x - 128;
        __nv_bfloat16* Wh = (__nv_bfloat16*)g_WhV;
        __nv_bfloat16* Wl = (__nv_bfloat16*)g_WlV;
        if (tid >= 128) return;
        if (b2 < 32) {
            int rr0 = 1024 + b2 * 8;
#pragma unroll
            for (int j = 0; j < 8; ++j) {
                int rr = rr0 + j;
                int row = 1792 + (rr - 1024);
                float v = W1[(size_t)row * 128 + tid];
                __nv_bfloat16 h = __float2bfloat16_rn(v);
                Wh[rr * 136 + tid] = h;
                Wl[rr * 136 + tid] = __float2bfloat16_rn(v - __bfloat162float(h));
            }
        } else if (b2 < 44) {
            int k = b2 - 32;
            int row0 = 1024 + (k / 3) * 192 + (k % 3) * 64;
            float s = 0.f;
#pragma unroll 8
            for (int d = 0; d < 64; ++d) s += W1[(size_t)(row0 + d) * 128 + tid];
            __nv_bfloat16 h = __float2bfloat16_rn(s);
            Wh[(1280 + k) * 136 + tid] = h;
            Wl[(1280 + k) * 136 + tid] = __float2bfloat16_rn(s - __bfloat162float(h));
        } else {
            __nv_bfloat16 z = __float2bfloat16_rn(0.f);
#pragma unroll
            for (int k = 12; k < 16; ++k) {
                Wh[(1280 + k) * 136 + tid] = z;
                Wl[(1280 + k) * 136 + tid] = z;
            }
        }
        return;
    }

    extern __shared__ char sm[];
    uint32 sb = smem_u32(sm);
    int lane = tid & 31, w = tid >> 5;
    int rb = (w >> 2) * 32, cb = (w & 3) * 32;
    int tg = blockIdx.x >> 1, khalf = blockIdx.x & 1;
    int tok0 = tg * 64;
    const float4* hidf4 = (const float4*)hidden;
    const float4* W1f4  = (const float4*)W1;

    float acc[2][4][4];
#pragma unroll
    for (int m = 0; m < 2; ++m)
#pragma unroll
        for (int n = 0; n < 4; ++n)
#pragma unroll
            for (int i = 0; i < 4; ++i) acc[m][n][i] = 0.f;

    float4 fa[4], fw[8];
    {
        int c = khalf * 8;
#pragma unroll
        for (int i = 0; i < 4; ++i) {
            int u = tid + 256 * i;
            fa[i] = hidf4[(size_t)(tok0 + (u >> 4)) * 256 + c * 16 + (u & 15)];
        }
#pragma unroll
        for (int i = 0; i < 8; ++i) {
            int u = tid + 256 * i;
            fw[i] = W1f4[(size_t)(c * 64 + (u >> 5)) * 32 + (u & 31)];
        }
    }

    for (int p = 0; p < 8; ++p) {
#pragma unroll
        for (int i = 0; i < 4; ++i) {
            int u = tid + 256 * i;
            int row = u >> 4, seg = u & 15;
            uint32 h0, l0, h1, l1;
            cvtpair(fa[i].x, fa[i].y, h0, l0);
            cvtpair(fa[i].z, fa[i].w, h1, l1);
            *(uint2*)(sm + row * 144 + seg * 8) = make_uint2(h0, h1);
            *(uint2*)(sm + P_ALO + row * 144 + seg * 8) = make_uint2(l0, l1);
        }
#pragma unroll
        for (int i = 0; i < 8; ++i) {
            int u = tid + 256 * i;
            int row = u >> 5, seg = u & 31;
            uint32 h0, l0, h1, l1;
            cvtpair(fw[i].x, fw[i].y, h0, l0);
            cvtpair(fw[i].z, fw[i].w, h1, l1);
            *(uint2*)(sm + P_BH + row * 272 + seg * 8) = make_uint2(h0, h1);
            *(uint2*)(sm + P_BL + row * 272 + seg * 8) = make_uint2(l0, l1);
        }
        if (p < 7) {
            int c = khalf * 8 + p + 1;
#pragma unroll
            for (int i = 0; i < 4; ++i) {
                int u = tid + 256 * i;
                fa[i] = hidf4[(size_t)(tok0 + (u >> 4)) * 256 + c * 16 + (u & 15)];
            }
#pragma unroll
            for (int i = 0; i < 8; ++i) {
                int u = tid + 256 * i;
                fw[i] = W1f4[(size_t)(c * 64 + (u >> 5)) * 32 + (u & 31)];
            }
        }
        __syncthreads();
        uint32 bbase = sb + P_BH + cb * 2;
        mma_chunk<4, 144>(acc, sb + rb * 144, sb + P_ALO + rb * 144,
                          bbase, bbase + 17408, lane);
        __syncthreads();
    }

    float* dst = g_hidc[khalf];
    int q4 = lane >> 2, q = lane & 3;
#pragma unroll
    for (int m = 0; m < 2; ++m)
#pragma unroll
        for (int nt = 0; nt < 4; ++nt) {
            int c0 = cb + nt * 8 + 2 * q;
            int rA = rb + 16 * m + q4;
            *(float2*)&dst[(size_t)(tok0 + rA) * 128 + c0] = make_float2(acc[m][nt][0], acc[m][nt][1]);
            *(float2*)&dst[(size_t)(tok0 + rA + 8) * 128 + c0] = make_float2(acc[m][nt][2], acc[m][nt][3]);
        }
}

// ============================================================================
// k_tail: grid 1024, 384 thr. Warps 0..7 consumers (mma), 8..11 producers.
// CTA = 4 tokens x 16 heads = 64 rows. Double-buffered A and B stages.
// smem: A[2] 0 (2x18432=36864) | B[2] 36864 (2x34816=69632)
//       ASH 106496 (3072) | ASL 109568 (3072) | HID 112640 (2048)
//       W2S 114688 (2048) | SHP 116736 (4096) | MSC 120832 (512)
//       MB 121344: full0 +0, full1 +8, empty0 +16, empty1 +24. Total 121376.
// ============================================================================
#define T_BB   36864
#define T_ASH  106496
#define T_ASL  109568
#define T_HID  112640
#define T_W2S  114688
#define T_SHP  116736
#define T_MSC  120832
#define T_MB   121344
#define T_SMEM 121376

__global__ void __launch_bounds__(384, 1) k_tail(
    const float* __restrict__ br0, const float* __restrict__ br1,
    const float* __restrict__ br2, const float* __restrict__ br3,
    const float* __restrict__ b1, const float* __restrict__ W2,
    const float* __restrict__ b2, const float* __restrict__ epsf,
    const float* __restrict__ temp, float* __restrict__ out) {
    extern __shared__ char sm[];
    uint32 sb = smem_u32(sm);
    int tid = threadIdx.x, lane = tid & 31, w = tid >> 5;
    int tok0 = blockIdx.x * 4;
    const float* brs[4] = {br0, br1, br2, br3};
    const char* WhB = (const char*)g_WhV;
    const char* WlB = (const char*)g_WlV;

    if (tid == 0) {
        MBAR_INIT(sb + T_MB + 0, 128);   // full0: 128 producer arrivals (+tx)
        MBAR_INIT(sb + T_MB + 8, 128);   // full1
        MBAR_INIT(sb + T_MB + 16, 256);  // empty0: 256 consumer arrivals
        MBAR_INIT(sb + T_MB + 24, 256);  // empty1
    }
    // prologue staging (all 384 threads present)
    if (tid < 128) {
        int row = tid >> 5, c4 = tid & 31;
        float4 a0 = *(const float4*)&g_hidc[0][(size_t)(tok0 + row) * 128 + c4 * 4];
        float4 a1 = *(const float4*)&g_hidc[1][(size_t)(tok0 + row) * 128 + c4 * 4];
        float4 c = ((const float4*)b1)[c4];
        *(float4*)(sm + T_HID + tid * 16) = make_float4(
            a0.x + a1.x + c.x, a0.y + a1.y + c.y, a0.z + a1.z + c.z, a0.w + a1.w + c.w);
        *(float4*)(sm + T_W2S + tid * 16) = ((const float4*)W2)[tid];
    }
    if (tid < 64) {
        *(uint2*)(sm + T_ASH + tid * 48 + 24) = make_uint2(0u, 0u);
        *(uint2*)(sm + T_ASL + tid * 48 + 24) = make_uint2(0u, 0u);
    }
    {
        float* msc = (float*)(sm + T_MSC);
        if (tid < 4)  msc[tid] = b2[tid];
        if (tid < 16) msc[4 + tid] = temp[tid];
        if (tid < 64) msc[20 + tid] = epsf[tid];
    }
    __syncthreads();   // LAST full-CTA barrier; roles diverge below

    if (w >= 8) {
        // ================= PRODUCER warps (8..11), 128 threads =================
        int ptid = tid - 256;            // 0..127
        uint32 phe0 = 0, phe1 = 0;
        for (int p = 0; p < 5; ++p) {
            int s = p & 1;
            if (p >= 2) {                // buffer reuse: wait consumers done
                if (s == 0) { mbar_wait(sb + T_MB + 16, phe0); phe0 ^= 1; }
                else        { mbar_wait(sb + T_MB + 24, phe1); phe1 ^= 1; }
            }
            if (p < 4) {
                char* Ab = sm + s * 18432;
#pragma unroll
                for (int i = 0; i < 8; ++i) {
                    int u = ptid + 128 * i;
                    float4 v = ((const float4*)brs[p])[(size_t)tok0 * 256 + u];
                    int row = u >> 4, seg = u & 15;
                    float st = v.x + v.y + v.z + v.w;
                    float s2 = fmaf(v.x, v.x, fmaf(v.y, v.y, fmaf(v.z, v.z, v.w * v.w)));
                    float mx = fmaxf(fmaxf(v.x, v.y), fmaxf(v.z, v.w));
#pragma unroll
                    for (int d = 1; d <= 8; d <<= 1) {
                        st += __shfl_xor_sync(0xffffffffu, st, d);
                        s2 += __shfl_xor_sync(0xffffffffu, s2, d);
                        mx = fmaxf(mx, __shfl_xor_sync(0xffffffffu, mx, d));
                    }
                    if (seg < 3) {
                        float sval = (seg == 0) ? st * 0.015625f
                                   : (seg == 1) ? sqrtf(fmaxf(s2 * 0.015625f, 1e-8f)) : mx;
                        __nv_bfloat16 h = __float2bfloat16_rn(sval);
                        *(__nv_bfloat16*)(sm + T_ASH + row * 48 + (p * 3 + seg) * 2) = h;
                        *(__nv_bfloat16*)(sm + T_ASL + row * 48 + (p * 3 + seg) * 2) =
                            __float2bfloat16_rn(sval - __bfloat162float(h));
                    }
                    uint32 h0, l0, h1, l1;
                    cvtpair(v.x, v.y, h0, l0);
                    cvtpair(v.z, v.w, h1, l1);
                    *(uint2*)(Ab + row * 144 + seg * 8) = make_uint2(h0, h1);
                    *(uint2*)(Ab + 9216 + row * 144 + seg * 8) = make_uint2(l0, l1);
                }
            }
            // B DMA + full arrivals
            if (ptid == 0) {
                int chunk = (p < 4) ? 16 + p : 20;
                uint32 bytes = (p < 4) ? 17408u : 4352u;
                uint32 bbuf = sb + T_BB + s * 34816;
                MBAR_EXPECT(sb + T_MB + s * 8, bytes * 2);   // counts as 1 arrival
                bulk_cp(bbuf, WhB + (size_t)chunk * 17408, bytes, sb + T_MB + s * 8);
                bulk_cp(bbuf + 17408, WlB + (size_t)chunk * 17408, bytes, sb + T_MB + s * 8);
            } else {
                MBAR_ARRIVE(sb + T_MB + s * 8);
            }
        }
        return;   // producers exit; no further CTA-wide barriers
    }

    // ================= CONSUMER warps (0..7), 256 threads =================
    int rowg = w >> 2, colg = w & 3;
    int rb = rowg * 32, cb = colg * 32;
    int q4 = lane >> 2, q = lane & 3;

    float acc[2][4][4];
#pragma unroll
    for (int m = 0; m < 2; ++m)
#pragma unroll
        for (int n = 0; n < 4; ++n)
#pragma unroll
            for (int i = 0; i < 4; ++i) acc[m][n][i] = 0.f;

    uint32 phf0 = 0, phf1 = 0;
    for (int p = 0; p < 5; ++p) {
        int s = p & 1;
        if (s == 0) { mbar_wait(sb + T_MB + 0, phf0); phf0 ^= 1; }
        else        { mbar_wait(sb + T_MB + 8, phf1); phf1 ^= 1; }
        uint32 bbase = sb + T_BB + s * 34816 + cb * 2;
        if (p < 4)
            mma_chunk<4, 144>(acc, sb + s * 18432 + rb * 144,
                              sb + s * 18432 + 9216 + rb * 144,
                              bbase, bbase + 17408, lane);
        else
            mma_chunk<1, 48>(acc, sb + T_ASH + rb * 48, sb + T_ASL + rb * 48,
                             bbase, bbase + 17408, lane);
        MBAR_ARRIVE(sb + T_MB + 16 + s * 8);
    }

    // ---- epilogue (consumers only; named barrier id 3, 256 threads) ----
    float lg[4][4];
#pragma unroll
    for (int s = 0; s < 4; ++s)
#pragma unroll
        for (int j = 0; j < 4; ++j) lg[s][j] = 0.f;
#pragma unroll
    for (int m = 0; m < 2; ++m) {
        int tokc = rowg * 2 + m;
#pragma unroll
        for (int nt = 0; nt < 4; ++nt) {
            int c0 = cb + nt * 8 + 2 * q;
            float2 hv = *(const float2*)(sm + T_HID + (tokc * 128 + c0) * 4);
            float4 wa = *(const float4*)(sm + T_W2S + c0 * 16);
            float4 wb = *(const float4*)(sm + T_W2S + (c0 + 1) * 16);
            float v0 = acc[m][nt][0] + hv.x, v1 = acc[m][nt][1] + hv.y;
            float v2 = acc[m][nt][2] + hv.x, v3 = acc[m][nt][3] + hv.y;
            float g0 = v0 * normcdff(v0), g1 = v1 * normcdff(v1);
            float g2 = v2 * normcdff(v2), g3 = v3 * normcdff(v3);
            lg[2 * m][0] = fmaf(g0, wa.x, fmaf(g1, wb.x, lg[2 * m][0]));
            lg[2 * m][1] = fmaf(g0, wa.y, fmaf(g1, wb.y, lg[2 * m][1]));
            lg[2 * m][2] = fmaf(g0, wa.z, fmaf(g1, wb.z, lg[2 * m][2]));
            lg[2 * m][3] = fmaf(g0, wa.w, fmaf(g1, wb.w, lg[2 * m][3]));
            lg[2 * m + 1][0] = fmaf(g2, wa.x, fmaf(g3, wb.x, lg[2 * m + 1][0]));
            lg[2 * m + 1][1] = fmaf(g2, wa.y, fmaf(g3, wb.y, lg[2 * m + 1][1]));
            lg[2 * m + 1][2] = fmaf(g2, wa.z, fmaf(g3, wb.z, lg[2 * m + 1][2]));
            lg[2 * m + 1][3] = fmaf(g2, wa.w, fmaf(g3, wb.w, lg[2 * m + 1][3]));
        }
    }
#pragma unroll
    for (int d = 1; d <= 2; d <<= 1)
#pragma unroll
        for (int s = 0; s < 4; ++s)
#pragma unroll
            for (int j = 0; j < 4; ++j)
                lg[s][j] += __shfl_xor_sync(0xffffffffu, lg[s][j], d);
    if (q == 0) {
#pragma unroll
        for (int s = 0; s < 4; ++s)
            *(float4*)(sm + T_SHP + (colg * 64 + rb + q4 + 8 * s) * 16) =
                make_float4(lg[s][0], lg[s][1], lg[s][2], lg[s][3]);
    }
    asm volatile("bar.sync 3, 256;" ::: "memory");

    if (tid < 64) {
        const float* msc = (const float*)(sm + T_MSC);
        int h = tid & 15;
        float l0 = msc[0], l1 = msc[1], l2 = msc[2], l3 = msc[3];
#pragma unroll
        for (int cg = 0; cg < 4; ++cg) {
            float4 pp = *(const float4*)(sm + T_SHP + (cg * 64 + tid) * 16);
            l0 += pp.x; l1 += pp.y; l2 += pp.z; l3 += pp.w;
        }
        float tt = fminf(fmaxf(msc[4 + h], 0.2f), 10.f);
        float it = 1.f / tt;
        float m = fmaxf(fmaxf(l0, l1), fmaxf(l2, l3));
        float e0 = expf((l0 - m) * it), e1 = expf((l1 - m) * it);
        float e2 = expf((l2 - m) * it), e3 = expf((l3 - m) * it);
        float inv = 1.f / (e0 + e1 + e2 + e3);
        float q0 = e0 * inv, q1 = e1 * inv, q2 = e2 * inv, q3 = e3 * inv;
        q0 = fmaxf(q0, fminf(fmaxf(msc[20 + h * 4 + 0], 1e-7f), 0.1f));
        q1 = fmaxf(q1, fminf(fmaxf(msc[20 + h * 4 + 1], 1e-7f), 0.1f));
        q2 = fmaxf(q2, fminf(fmaxf(msc[20 + h * 4 + 2], 1e-7f), 0.1f));
        q3 = fmaxf(q3, fminf(fmaxf(msc[20 + h * 4 + 3], 1e-7f), 0.1f));
        inv = 1.f / (q0 + q1 + q2 + q3);
        *(float4*)&out[(size_t)(tok0 * 16 + tid) * 4] =
            make_float4(q0 * inv, q1 * inv, q2 * inv, q3 * inv);
    }
}

extern "C" void kernel_launch(void* const* d_in, const int* in_sizes, int n_in,
                              void* d_out, int out_size) {
    const float* hidden = (const float*)d_in[0];
    const float* br0    = (const float*)d_in[1];
    const float* br1    = (const float*)d_in[2];
    const float* br2    = (const float*)d_in[3];
    const float* br3    = (const float*)d_in[4];
    const float* W1     = (const float*)d_in[5];
    const float* b1     = (const float*)d_in[6];
    const float* W2     = (const float*)d_in[7];
    const float* b2     = (const float*)d_in[8];
    const float* epsf   = (const float*)d_in[9];
    const float* temp   = (const float*)d_in[10];
    float* out = (float*)d_out;

    cudaFuncSetAttribute(k_pre,  cudaFuncAttributeMaxDynamicSharedMemorySize, P_SMEM);
    cudaFuncSetAttribute(k_tail, cudaFuncAttributeMaxDynamicSharedMemorySize, T_SMEM);

    k_pre<<<173, 256, P_SMEM>>>(hidden, W1);
    k_tail<<<1024, 384, T_SMEM>>>(br0, br1, br2, br3, b1, W2, b2, epsf, temp, out);
}

// round 16
// speedup vs baseline: 2.3784x; 2.3784x over previous
#include <cuda_runtime.h>
#include <cuda_bf16.h>
#include <math.h>

typedef unsigned int uint32;

// ============================================================================
// HeadGroupedFusionGate, mma.sync bf16 3-term split (x*w ~ xh*wh + xl*wh + xh*wl).
// R14: R11 base (3 CTAs/SM, single-buffer A/B, bulk-DMA B) with the convert
//      phase shrunk: row-local stats (4 lanes/row, 2-step shfl instead of
//      per-i 4-step chains), statw B preloaded at prologue (5th DMA phase
//      deleted), SHP aliased into the A buffer.
// ============================================================================

__device__ uint4 g_WhV[21 * 1088];    // B: [chunk][k=64][n=136 pad] bf16
__device__ uint4 g_WlV[21 * 1088];
__device__ float g_hidc[2][4096 * 128];

// ---- PTX helpers ----
__device__ __forceinline__ uint32 smem_u32(const void* p) {
    uint32 a;
    asm("{ .reg .u64 t; cvta.to.shared.u64 t, %1; cvt.u32.u64 %0, t; }" : "=r"(a) : "l"(p));
    return a;
}
__device__ __forceinline__ void ldsm4(uint32* r, uint32 a) {
    asm volatile("ldmatrix.sync.aligned.m8n8.x4.shared.b16 {%0,%1,%2,%3}, [%4];"
        : "=r"(r[0]), "=r"(r[1]), "=r"(r[2]), "=r"(r[3]) : "r"(a));
}
__device__ __forceinline__ void ldsm4t(uint32* r, uint32 a) {
    asm volatile("ldmatrix.sync.aligned.m8n8.x4.trans.shared.b16 {%0,%1,%2,%3}, [%4];"
        : "=r"(r[0]), "=r"(r[1]), "=r"(r[2]), "=r"(r[3]) : "r"(a));
}
__device__ __forceinline__ void mma16816(float* d, const uint32* a, uint32 b0, uint32 b1) {
    asm volatile("mma.sync.aligned.m16n8k16.row.col.f32.bf16.bf16.f32 "
        "{%0,%1,%2,%3}, {%4,%5,%6,%7}, {%8,%9}, {%0,%1,%2,%3};"
        : "+f"(d[0]), "+f"(d[1]), "+f"(d[2]), "+f"(d[3])
        : "r"(a[0]), "r"(a[1]), "r"(a[2]), "r"(a[3]), "r"(b0), "r"(b1));
}
__device__ __forceinline__ void cvtpair(float v0, float v1, uint32& h, uint32& l) {
    __nv_bfloat162 hp = __floats2bfloat162_rn(v0, v1);
    h = *(uint32*)&hp;
    float r0 = v0 - __bfloat162float(hp.x);
    float r1 = v1 - __bfloat162float(hp.y);
    __nv_bfloat162 lp = __floats2bfloat162_rn(r0, r1);
    l = *(uint32*)&lp;
}
#define MBAR_INIT(mb, n) \
    asm volatile("mbarrier.init.shared.b64 [%0], %1;" :: "r"(mb), "r"(n) : "memory")
#define MBAR_EXPECT(mb, tx) \
    asm volatile("mbarrier.arrive.expect_tx.shared.b64 _, [%0], %1;" :: "r"(mb), "r"(tx) : "memory")
__device__ __forceinline__ void bulk_cp(uint32 dst, const void* src, uint32 bytes, uint32 mb) {
    asm volatile("cp.async.bulk.shared::cta.global.mbarrier::complete_tx::bytes "
                 "[%0], [%1], %2, [%3];" :: "r"(dst), "l"(src), "r"(bytes), "r"(mb) : "memory");
}
__device__ __forceinline__ void mbar_wait(uint32 mb, uint32 parity) {
    asm volatile(
        "{\n\t.reg .pred P;\n\t"
        "W%=:\n\tmbarrier.try_wait.parity.acquire.cta.shared::cta.b64 P, [%0], %1, 0x989680;\n\t"
        "@P bra.uni D%=;\n\tbra.uni W%=;\n\tD%=:\n\t}"
        :: "r"(mb), "r"(parity) : "memory");
}

// warp tile 32 rows x 32 cols; NK k16 steps; low-register (one 16-col B half live).
template <int NK, int SA>
__device__ __forceinline__ void mma_chunk(float (&acc)[2][4][4],
                                          uint32 Ah, uint32 Al,
                                          uint32 Bh, uint32 Bl, int lane) {
    uint32 aoff = (uint32)((lane & 15) * SA + (lane >> 4) * 16);
    uint32 boff = (uint32)(((lane & 7) + ((lane >> 3) & 1) * 8) * 272 + ((lane >> 4) & 1) * 16);
#pragma unroll
    for (int k = 0; k < NK; ++k) {
        uint32 ah[2][4], al[2][4];
        ldsm4(ah[0], Ah + aoff + k * 32);
        ldsm4(ah[1], Ah + 16 * SA + aoff + k * 32);
        ldsm4(al[0], Al + aoff + k * 32);
        ldsm4(al[1], Al + 16 * SA + aoff + k * 32);
        uint32 bb = boff + k * 4352;
#pragma unroll
        for (int half = 0; half < 2; ++half) {
            uint32 bh[4], bl[4];
            ldsm4t(bh, Bh + bb + half * 32);
            ldsm4t(bl, Bl + bb + half * 32);
#pragma unroll
            for (int m = 0; m < 2; ++m) {
                mma16816(acc[m][2 * half + 0], ah[m], bh[0], bh[1]);
                mma16816(acc[m][2 * half + 1], ah[m], bh[2], bh[3]);
                mma16816(acc[m][2 * half + 0], al[m], bh[0], bh[1]);
                mma16816(acc[m][2 * half + 1], al[m], bh[2], bh[3]);
                mma16816(acc[m][2 * half + 0], ah[m], bl[0], bl[1]);
                mma16816(acc[m][2 * half + 1], ah[m], bl[2], bl[3]);
            }
        }
    }
}

// ============================================================================
// k_pre (R11): blocks 0..127 hidden GEMM, 128..172 tail-weight prep.
// smem (hid): AHI 0 (9216) | ALO 9216 | BH 18432 (17408) | BL 35840. = 53248.
// ============================================================================
#define P_ALO  9216
#define P_BH   18432
#define P_BL   35840
#define P_SMEM 53248

__global__ void __launch_bounds__(256) k_pre(const float* __restrict__ hidden,
                                             const float* __restrict__ W1) {
    int tid = threadIdx.x;
    if (blockIdx.x >= 128) {
        int b2 = blockIdx.x - 128;
        __nv_bfloat16* Wh = (__nv_bfloat16*)g_WhV;
        __nv_bfloat16* Wl = (__nv_bfloat16*)g_WlV;
        if (tid >= 128) return;
        if (b2 < 32) {
            int rr0 = 1024 + b2 * 8;
#pragma unroll
            for (int j = 0; j < 8; ++j) {
                int rr = rr0 + j;
                int row = 1792 + (rr - 1024);
                float v = W1[(size_t)row * 128 + tid];
                __nv_bfloat16 h = __float2bfloat16_rn(v);
                Wh[rr * 136 + tid] = h;
                Wl[rr * 136 + tid] = __float2bfloat16_rn(v - __bfloat162float(h));
            }
        } else if (b2 < 44) {
            int k = b2 - 32;
            int row0 = 1024 + (k / 3) * 192 + (k % 3) * 64;
            float s = 0.f;
#pragma unroll 8
            for (int d = 0; d < 64; ++d) s += W1[(size_t)(row0 + d) * 128 + tid];
            __nv_bfloat16 h = __float2bfloat16_rn(s);
            Wh[(1280 + k) * 136 + tid] = h;
            Wl[(1280 + k) * 136 + tid] = __float2bfloat16_rn(s - __bfloat162float(h));
        } else {
            __nv_bfloat16 z = __float2bfloat16_rn(0.f);
#pragma unroll
            for (int k = 12; k < 16; ++k) {
                Wh[(1280 + k) * 136 + tid] = z;
                Wl[(1280 + k) * 136 + tid] = z;
            }
        }
        return;
    }

    extern __shared__ char sm[];
    uint32 sb = smem_u32(sm);
    int lane = tid & 31, w = tid >> 5;
    int rb = (w >> 2) * 32, cb = (w & 3) * 32;
    int tg = blockIdx.x >> 1, khalf = blockIdx.x & 1;
    int tok0 = tg * 64;
    const float4* hidf4 = (const float4*)hidden;
    const float4* W1f4  = (const float4*)W1;

    float acc[2][4][4];
#pragma unroll
    for (int m = 0; m < 2; ++m)
#pragma unroll
        for (int n = 0; n < 4; ++n)
#pragma unroll
            for (int i = 0; i < 4; ++i) acc[m][n][i] = 0.f;

    float4 fa[4], fw[8];
    {
        int c = khalf * 8;
#pragma unroll
        for (int i = 0; i < 4; ++i) {
            int u = tid + 256 * i;
            fa[i] = hidf4[(size_t)(tok0 + (u >> 4)) * 256 + c * 16 + (u & 15)];
        }
#pragma unroll
        for (int i = 0; i < 8; ++i) {
            int u = tid + 256 * i;
            fw[i] = W1f4[(size_t)(c * 64 + (u >> 5)) * 32 + (u & 31)];
        }
    }

    for (int p = 0; p < 8; ++p) {
#pragma unroll
        for (int i = 0; i < 4; ++i) {
            int u = tid + 256 * i;
            int row = u >> 4, seg = u & 15;
            uint32 h0, l0, h1, l1;
            cvtpair(fa[i].x, fa[i].y, h0, l0);
            cvtpair(fa[i].z, fa[i].w, h1, l1);
            *(uint2*)(sm + row * 144 + seg * 8) = make_uint2(h0, h1);
            *(uint2*)(sm + P_ALO + row * 144 + seg * 8) = make_uint2(l0, l1);
        }
#pragma unroll
        for (int i = 0; i < 8; ++i) {
            int u = tid + 256 * i;
            int row = u >> 5, seg = u & 31;
            uint32 h0, l0, h1, l1;
            cvtpair(fw[i].x, fw[i].y, h0, l0);
            cvtpair(fw[i].z, fw[i].w, h1, l1);
            *(uint2*)(sm + P_BH + row * 272 + seg * 8) = make_uint2(h0, h1);
            *(uint2*)(sm + P_BL + row * 272 + seg * 8) = make_uint2(l0, l1);
        }
        if (p < 7) {
            int c = khalf * 8 + p + 1;
#pragma unroll
            for (int i = 0; i < 4; ++i) {
                int u = tid + 256 * i;
                fa[i] = hidf4[(size_t)(tok0 + (u >> 4)) * 256 + c * 16 + (u & 15)];
            }
#pragma unroll
            for (int i = 0; i < 8; ++i) {
                int u = tid + 256 * i;
                fw[i] = W1f4[(size_t)(c * 64 + (u >> 5)) * 32 + (u & 31)];
            }
        }
        __syncthreads();
        uint32 bbase = sb + P_BH + cb * 2;
        mma_chunk<4, 144>(acc, sb + rb * 144, sb + P_ALO + rb * 144,
                          bbase, bbase + 17408, lane);
        __syncthreads();
    }

    float* dst = g_hidc[khalf];
    int q4 = lane >> 2, q = lane & 3;
#pragma unroll
    for (int m = 0; m < 2; ++m)
#pragma unroll
        for (int nt = 0; nt < 4; ++nt) {
            int c0 = cb + nt * 8 + 2 * q;
            int rA = rb + 16 * m + q4;
            *(float2*)&dst[(size_t)(tok0 + rA) * 128 + c0] = make_float2(acc[m][nt][0], acc[m][nt][1]);
            *(float2*)&dst[(size_t)(tok0 + rA + 8) * 128 + c0] = make_float2(acc[m][nt][2], acc[m][nt][3]);
        }
}

// ============================================================================
// k_tail: grid 1024, 256 thr = 8 warps, 3 CTAs/SM. CTA = 4 tokens x 16 heads.
// smem: A 0 (18432; SHP 4096 aliased at 0 for epilogue) | B 18432 (34816)
//       ASH 53248 (3072) | ASL 56320 (3072) | SW 59392 (8704: statw hi|lo)
//       HID 68096 (2048) | W2S 70144 (2048) | MSC 72192 (512) | MB 72704 (8)
//       Total 72720.
// ============================================================================
#define T_BB   18432
#define T_ASH  53248
#define T_ASL  56320
#define T_SW   59392
#define T_HID  68096
#define T_W2S  70144
#define T_MSC  72192
#define T_MB   72704
#define T_SMEM 72720

__global__ void __launch_bounds__(256, 3) k_tail(
    const float* __restrict__ br0, const float* __restrict__ br1,
    const float* __restrict__ br2, const float* __restrict__ br3,
    const float* __restrict__ b1, const float* __restrict__ W2,
    const float* __restrict__ b2, const float* __restrict__ epsf,
    const float* __restrict__ temp, float* __restrict__ out) {
    extern __shared__ char sm[];
    uint32 sb = smem_u32(sm);
    int tid = threadIdx.x, lane = tid & 31, w = tid >> 5;
    int rowg = w >> 2, colg = w & 3;
    int rb = rowg * 32, cb = colg * 32;
    int q4 = lane >> 2, q = lane & 3;
    int tok0 = blockIdx.x * 4;
    const float* brs[4] = {br0, br1, br2, br3};
    const char* WhB = (const char*)g_WhV;
    const char* WlB = (const char*)g_WlV;

    if (tid == 0) {
        MBAR_INIT(sb + T_MB, 1);
        MBAR_EXPECT(sb + T_MB, 34816u);
        bulk_cp(sb + T_BB, WhB + (size_t)16 * 17408, 17408u, sb + T_MB);
        bulk_cp(sb + T_BB + 17408, WlB + (size_t)16 * 17408, 17408u, sb + T_MB);
    }
    // prologue staging: statw (chunk 20, 16 rows hi+lo), epilogue data, stat pad
    for (int u = tid; u < 544; u += 256) {
        const uint4* src = (u < 272) ? (const uint4*)(WhB + (size_t)20 * 17408) + u
                                     : (const uint4*)(WlB + (size_t)20 * 17408) + (u - 272);
        ((uint4*)(sm + T_SW))[u] = *src;
    }
    if (tid < 128) {
        int row = tid >> 5, c4 = tid & 31;
        float4 a0 = *(const float4*)&g_hidc[0][(size_t)(tok0 + row) * 128 + c4 * 4];
        float4 a1 = *(const float4*)&g_hidc[1][(size_t)(tok0 + row) * 128 + c4 * 4];
        float4 c = ((const float4*)b1)[c4];
        *(float4*)(sm + T_HID + tid * 16) = make_float4(
            a0.x + a1.x + c.x, a0.y + a1.y + c.y, a0.z + a1.z + c.z, a0.w + a1.w + c.w);
        *(float4*)(sm + T_W2S + tid * 16) = ((const float4*)W2)[tid];
    }
    if (tid < 64) {
        *(uint2*)(sm + T_ASH + tid * 48 + 24) = make_uint2(0u, 0u);
        *(uint2*)(sm + T_ASL + tid * 48 + 24) = make_uint2(0u, 0u);
    }
    {
        float* msc = (float*)(sm + T_MSC);
        if (tid < 4)  msc[tid] = b2[tid];
        if (tid < 16) msc[4 + tid] = temp[tid];
        if (tid < 64) msc[20 + tid] = epsf[tid];
    }

    float acc[2][4][4];
#pragma unroll
    for (int m = 0; m < 2; ++m)
#pragma unroll
        for (int n = 0; n < 4; ++n)
#pragma unroll
            for (int i = 0; i < 4; ++i) acc[m][n][i] = 0.f;

    int arow = tid >> 2, sl = tid & 3;     // convert mapping: 4 lanes per row
    uint32 ph = 0;
    for (int p = 0; p < 4; ++p) {
        if (p > 0) {
            __syncthreads();               // mma(p-1) done: A + B free
            if (tid == 0) {
                MBAR_EXPECT(sb + T_MB, 34816u);
                bulk_cp(sb + T_BB, WhB + (size_t)(16 + p) * 17408, 17408u, sb + T_MB);
                bulk_cp(sb + T_BB + 17408, WlB + (size_t)(16 + p) * 17408, 17408u, sb + T_MB);
            }
        }
        // convert phase: 4 LDGs from the SAME row -> local stats, 2-step shfl
        {
            const float4* src = (const float4*)brs[p] + (size_t)tok0 * 256 + arow * 16 + sl;
            float4 v0 = src[0];
            float4 v1 = src[4];
            float4 v2 = src[8];
            float4 v3 = src[12];
            float s = (v0.x + v0.y + v0.z + v0.w) + (v1.x + v1.y + v1.z + v1.w)
                    + (v2.x + v2.y + v2.z + v2.w) + (v3.x + v3.y + v3.z + v3.w);
            float s2 = 0.f;
            s2 = fmaf(v0.x, v0.x, fmaf(v0.y, v0.y, fmaf(v0.z, v0.z, fmaf(v0.w, v0.w, s2))));
            s2 = fmaf(v1.x, v1.x, fmaf(v1.y, v1.y, fmaf(v1.z, v1.z, fmaf(v1.w, v1.w, s2))));
            s2 = fmaf(v2.x, v2.x, fmaf(v2.y, v2.y, fmaf(v2.z, v2.z, fmaf(v2.w, v2.w, s2))));
            s2 = fmaf(v3.x, v3.x, fmaf(v3.y, v3.y, fmaf(v3.z, v3.z, fmaf(v3.w, v3.w, s2))));
            float mx = fmaxf(fmaxf(fmaxf(v0.x, v0.y), fmaxf(v0.z, v0.w)),
                             fmaxf(fmaxf(v1.x, v1.y), fmaxf(v1.z, v1.w)));
            mx = fmaxf(mx, fmaxf(fmaxf(fmaxf(v2.x, v2.y), fmaxf(v2.z, v2.w)),
                                 fmaxf(fmaxf(v3.x, v3.y), fmaxf(v3.z, v3.w))));
#pragma unroll
            for (int d = 1; d <= 2; d <<= 1) {
                s += __shfl_xor_sync(0xffffffffu, s, d);
                s2 += __shfl_xor_sync(0xffffffffu, s2, d);
                mx = fmaxf(mx, __shfl_xor_sync(0xffffffffu, mx, d));
            }
            if (sl == 0) {
                float v3s[3];
                v3s[0] = s * 0.015625f;
                v3s[1] = sqrtf(fmaxf(s2 * 0.015625f, 1e-8f));
                v3s[2] = mx;
#pragma unroll
                for (int j = 0; j < 3; ++j) {
                    __nv_bfloat16 h = __float2bfloat16_rn(v3s[j]);
                    *(__nv_bfloat16*)(sm + T_ASH + arow * 48 + (p * 3 + j) * 2) = h;
                    *(__nv_bfloat16*)(sm + T_ASL + arow * 48 + (p * 3 + j) * 2) =
                        __float2bfloat16_rn(v3s[j] - __bfloat162float(h));
                }
            }
            float4 vv[4] = {v0, v1, v2, v3};
#pragma unroll
            for (int j = 0; j < 4; ++j) {
                int seg = sl + 4 * j;
                uint32 h0, l0, h1, l1;
                cvtpair(vv[j].x, vv[j].y, h0, l0);
                cvtpair(vv[j].z, vv[j].w, h1, l1);
                *(uint2*)(sm + arow * 144 + seg * 8) = make_uint2(h0, h1);
                *(uint2*)(sm + 9216 + arow * 144 + seg * 8) = make_uint2(l0, l1);
            }
        }
        __syncthreads();                   // A(p) visible
        mbar_wait(sb + T_MB, ph); ph ^= 1; // B(p) arrived
        uint32 bbase = sb + T_BB + cb * 2;
        mma_chunk<4, 144>(acc, sb + rb * 144, sb + 9216 + rb * 144,
                          bbase, bbase + 17408, lane);
    }
    // stats chunk: A from ASH/ASL, B from preloaded SW — no DMA, no extra sync
    mma_chunk<1, 48>(acc, sb + T_ASH + rb * 48, sb + T_ASL + rb * 48,
                     sb + T_SW + cb * 2, sb + T_SW + 4352 + cb * 2, lane);

    __syncthreads();   // all mma done before SHP (aliased over A buffer) writes

    // ---- epilogue: gelu + W2 partial logits; SHP at smem offset 0 ----
    float lg[4][4];
#pragma unroll
    for (int s = 0; s < 4; ++s)
#pragma unroll
        for (int j = 0; j < 4; ++j) lg[s][j] = 0.f;
#pragma unroll
    for (int m = 0; m < 2; ++m) {
        int tokc = rowg * 2 + m;
#pragma unroll
        for (int nt = 0; nt < 4; ++nt) {
            int c0 = cb + nt * 8 + 2 * q;
            float2 hv = *(const float2*)(sm + T_HID + (tokc * 128 + c0) * 4);
            float4 wa = *(const float4*)(sm + T_W2S + c0 * 16);
            float4 wb = *(const float4*)(sm + T_W2S + (c0 + 1) * 16);
            float v0 = acc[m][nt][0] + hv.x, v1 = acc[m][nt][1] + hv.y;
            float v2 = acc[m][nt][2] + hv.x, v3 = acc[m][nt][3] + hv.y;
            float g0 = v0 * normcdff(v0), g1 = v1 * normcdff(v1);
            float g2 = v2 * normcdff(v2), g3 = v3 * normcdff(v3);
            lg[2 * m][0] = fmaf(g0, wa.x, fmaf(g1, wb.x, lg[2 * m][0]));
            lg[2 * m][1] = fmaf(g0, wa.y, fmaf(g1, wb.y, lg[2 * m][1]));
            lg[2 * m][2] = fmaf(g0, wa.z, fmaf(g1, wb.z, lg[2 * m][2]));
            lg[2 * m][3] = fmaf(g0, wa.w, fmaf(g1, wb.w, lg[2 * m][3]));
            lg[2 * m + 1][0] = fmaf(g2, wa.x, fmaf(g3, wb.x, lg[2 * m + 1][0]));
            lg[2 * m + 1][1] = fmaf(g2, wa.y, fmaf(g3, wb.y, lg[2 * m + 1][1]));
            lg[2 * m + 1][2] = fmaf(g2, wa.z, fmaf(g3, wb.z, lg[2 * m + 1][2]));
            lg[2 * m + 1][3] = fmaf(g2, wa.w, fmaf(g3, wb.w, lg[2 * m + 1][3]));
        }
    }
#pragma unroll
    for (int d = 1; d <= 2; d <<= 1)
#pragma unroll
        for (int s = 0; s < 4; ++s)
#pragma unroll
            for (int j = 0; j < 4; ++j)
                lg[s][j] += __shfl_xor_sync(0xffffffffu, lg[s][j], d);
    if (q == 0) {
#pragma unroll
        for (int s = 0; s < 4; ++s)
            *(float4*)(sm + (colg * 64 + rb + q4 + 8 * s) * 16) =
                make_float4(lg[s][0], lg[s][1], lg[s][2], lg[s][3]);
    }
    __syncthreads();

    if (tid < 64) {
        const float* msc = (const float*)(sm + T_MSC);
        int h = tid & 15;
        float l0 = msc[0], l1 = msc[1], l2 = msc[2], l3 = msc[3];
#pragma unroll
        for (int cg = 0; cg < 4; ++cg) {
            float4 pp = *(const float4*)(sm + (cg * 64 + tid) * 16);
            l0 += pp.x; l1 += pp.y; l2 += pp.z; l3 += pp.w;
        }
        float tt = fminf(fmaxf(msc[4 + h], 0.2f), 10.f);
        float it = 1.f / tt;
        float m = fmaxf(fmaxf(l0, l1), fmaxf(l2, l3));
        float e0 = expf((l0 - m) * it), e1 = expf((l1 - m) * it);
        float e2 = expf((l2 - m) * it), e3 = expf((l3 - m) * it);
        float inv = 1.f / (e0 + e1 + e2 + e3);
        float q0 = e0 * inv, q1 = e1 * inv, q2 = e2 * inv, q3 = e3 * inv;
        q0 = fmaxf(q0, fminf(fmaxf(msc[20 + h * 4 + 0], 1e-7f), 0.1f));
        q1 = fmaxf(q1, fminf(fmaxf(msc[20 + h * 4 + 1], 1e-7f), 0.1f));
        q2 = fmaxf(q2, fminf(fmaxf(msc[20 + h * 4 + 2], 1e-7f), 0.1f));
        q3 = fmaxf(q3, fminf(fmaxf(msc[20 + h * 4 + 3], 1e-7f), 0.1f));
        inv = 1.f / (q0 + q1 + q2 + q3);
        *(float4*)&out[(size_t)(tok0 * 16 + tid) * 4] =
            make_float4(q0 * inv, q1 * inv, q2 * inv, q3 * inv);
    }
}

extern "C" void kernel_launch(void* const* d_in, const int* in_sizes, int n_in,
                              void* d_out, int out_size) {
    const float* hidden = (const float*)d_in[0];
    const float* br0    = (const float*)d_in[1];
    const float* br1    = (const float*)d_in[2];
    const float* br2    = (const float*)d_in[3];
    const float* br3    = (const float*)d_in[4];
    const float* W1     = (const float*)d_in[5];
    const float* b1     = (const float*)d_in[6];
    const float* W2     = (const float*)d_in[7];
    const float* b2     = (const float*)d_in[8];
    const float* epsf   = (const float*)d_in[9];
    const float* temp   = (const float*)d_in[10];
    float* out = (float*)d_out;

    cudaFuncSetAttribute(k_pre,  cudaFuncAttributeMaxDynamicSharedMemorySize, P_SMEM);
    cudaFuncSetAttribute(k_tail, cudaFuncAttributeMaxDynamicSharedMemorySize, T_SMEM);

    k_pre<<<173, 256, P_SMEM>>>(hidden, W1);
    k_tail<<<1024, 256, T_SMEM>>>(br0, br1, br2, br3, b1, W2, b2, epsf, temp, out);
}